// round 11
// baseline (speedup 1.0000x reference)
#include <cuda_runtime.h>
#include <math.h>
#include <stdint.h>

// Problem dims (fixed by the dataset)
#define Bq 4
#define Tq 2048
#define Dq 1024
#define Hq 2048
#define Eq 8
#define Kq 2
#define Nq (Bq*Tq)          // 8192 tokens
#define NROWS (Nq*Kq)       // 16384 (token, expert) pairs
#define MTILES 64           // worst case: one expert gets all 8192 tokens

// GEMM tiling
#define KT 32               // k-tile
#define AS_STRIDE 40        // floats per A smem row (128 rows); 40%32==8 -> conflict-free f2
#define BS_STRIDE 132       // floats per B smem row (32 rows); 132%32==4 -> conflict-free
#define A_STAGE_F (128*AS_STRIDE)          // 5120 floats
#define B_STAGE_F (KT*BS_STRIDE)           // 4224 floats
#define STAGE_F   (A_STAGE_F + B_STAGE_F)  // 9344 floats = 37376 B
#define SMEM_BYTES (2*STAGE_F*4)           // 74752 B

// -------------------- scratch (device globals; no allocation allowed) ------
__device__ int   g_count[Eq];
__device__ int   g_offset[Eq];
__device__ int   g_cursor[Eq];
__device__ float g_imp_sum[Eq];
__device__ float g_ent_sum;
__device__ int   g_tk_idx[Nq*Kq];
__device__ float g_tk_gate[Nq*Kq];
__device__ int   g_row_token[NROWS];
__device__ float g_row_gate[NROWS];
__device__ float g_h[(size_t)NROWS*Hq];   // 128 MiB intermediate (gelu output)
__device__ float g_z[(size_t)Nq*Dq];      // residual accumulator (x + moe_out)

// -------------------- helpers ---------------------------------------------
__device__ __forceinline__ void mma8(float* d,
                                     uint32_t a0, uint32_t a1, uint32_t a2, uint32_t a3,
                                     uint32_t b0, uint32_t b1) {
    asm volatile("mma.sync.aligned.m16n8k8.row.col.f32.tf32.tf32.f32 "
                 "{%0,%1,%2,%3}, {%4,%5,%6,%7}, {%8,%9}, {%0,%1,%2,%3};"
                 : "+f"(d[0]), "+f"(d[1]), "+f"(d[2]), "+f"(d[3])
                 : "r"(a0), "r"(a1), "r"(a2), "r"(a3), "r"(b0), "r"(b1));
}

__device__ __forceinline__ void cp16(uint32_t dst, const void* src, int szr) {
    asm volatile("cp.async.cg.shared.global [%0], [%1], 16, %2;"
                 :: "r"(dst), "l"(src), "r"(szr));
}
#define CP_COMMIT() asm volatile("cp.async.commit_group;")
#define CP_WAIT0()  asm volatile("cp.async.wait_group 0;")

__device__ __forceinline__ float gelu_exact(float c) {
    return 0.5f * c * (1.f + erff(c * 0.70710678118654752f));
}

// -------------------- init ------------------------------------------------
__global__ void init_k() {
    int i = threadIdx.x;
    if (i < Eq) { g_count[i] = 0; g_imp_sum[i] = 0.f; }
    if (i == Eq) g_ent_sum = 0.f;
}

// -------------------- router: one warp per token --------------------------
__global__ void router_k(const float* __restrict__ x,
                         const float* __restrict__ gw,
                         const float* __restrict__ gb) {
    __shared__ float s_imp[Eq];
    __shared__ int   s_cnt[Eq];
    __shared__ float s_ent;
    int tid = threadIdx.x;
    if (tid < Eq) { s_imp[tid] = 0.f; s_cnt[tid] = 0; }
    if (tid == Eq) s_ent = 0.f;
    __syncthreads();

    int warp = tid >> 5, lane = tid & 31;
    int t = blockIdx.x * 8 + warp;

    float acc[Eq];
    #pragma unroll
    for (int e = 0; e < Eq; e++) acc[e] = 0.f;

    const float* xr = x + (size_t)t * Dq;
    for (int d = lane; d < Dq; d += 32) {
        float xv = xr[d];
        const float* gwr = gw + d * Eq;
        #pragma unroll
        for (int e = 0; e < Eq; e++) acc[e] += xv * gwr[e];
    }
    #pragma unroll
    for (int e = 0; e < Eq; e++) {
        #pragma unroll
        for (int o = 16; o > 0; o >>= 1)
            acc[e] += __shfl_down_sync(0xffffffffu, acc[e], o);
    }

    if (lane == 0) {
        float lg[Eq], p[Eq];
        float mx = -1e30f;
        #pragma unroll
        for (int e = 0; e < Eq; e++) { lg[e] = acc[e] + gb[e]; mx = fmaxf(mx, lg[e]); }
        float se = 0.f;
        #pragma unroll
        for (int e = 0; e < Eq; e++) { p[e] = expf(lg[e] - mx); se += p[e]; }
        float inv = 1.f / se;
        float ent = 0.f;
        #pragma unroll
        for (int e = 0; e < Eq; e++) {
            p[e] *= inv;
            ent -= p[e] * logf(p[e] + 1e-8f);
            atomicAdd(&s_imp[e], p[e]);
        }
        float bv = -1e30f, sv = -1e30f; int bi = 0, si = 0;
        #pragma unroll
        for (int e = 0; e < Eq; e++) {
            float v = lg[e];
            if (v > bv) { sv = bv; si = bi; bv = v; bi = e; }
            else if (v > sv) { sv = v; si = e; }
        }
        float g0 = 1.f / (1.f + expf(sv - bv));
        float g1 = 1.f - g0;
        g_tk_idx[2*t]   = bi;  g_tk_idx[2*t+1]  = si;
        g_tk_gate[2*t]  = g0;  g_tk_gate[2*t+1] = g1;
        atomicAdd(&s_cnt[bi], 1);
        atomicAdd(&s_cnt[si], 1);
        atomicAdd(&s_ent, ent);
    }
    __syncthreads();
    if (tid < Eq) {
        if (s_cnt[tid]) atomicAdd(&g_count[tid], s_cnt[tid]);
        atomicAdd(&g_imp_sum[tid], s_imp[tid]);
    }
    if (tid == Eq) atomicAdd(&g_ent_sum, s_ent);
}

// -------------------- finalize scalars + prefix offsets -------------------
__global__ void finalize_k(float* __restrict__ out_tail) {
    if (threadIdx.x != 0) return;
    int c = 0;
    #pragma unroll
    for (int e = 0; e < Eq; e++) { g_offset[e] = c; g_cursor[e] = c; c += g_count[e]; }
    float invN = 1.f / (float)Nq;
    float bal = 0.f, ue = 0.f;
    #pragma unroll
    for (int e = 0; e < Eq; e++) {
        float imp  = g_imp_sum[e] * invN;
        float load = (float)g_count[e] * invN;
        bal += imp * load;
        ue  -= load * logf(load + 1e-8f);
        out_tail[3 + e]  = load;
        out_tail[11 + e] = imp;
    }
    out_tail[0] = (float)Eq * bal;
    out_tail[1] = g_ent_sum * invN;
    out_tail[2] = ue;
}

// -------------------- scatter: compact per-expert row lists ---------------
__global__ void scatter_k() {
    int t = blockIdx.x * blockDim.x + threadIdx.x;
    if (t >= Nq) return;
    #pragma unroll
    for (int k = 0; k < Kq; k++) {
        int e = g_tk_idx[2*t + k];
        int pos = atomicAdd(&g_cursor[e], 1);
        g_row_token[pos] = t;
        g_row_gate[pos]  = g_tk_gate[2*t + k];
    }
}

// -------------------- z = x (residual init) -------------------------------
__global__ void zinit_k(const float* __restrict__ x) {
    size_t i = (size_t)blockIdx.x * blockDim.x + threadIdx.x;
    reinterpret_cast<float4*>(g_z)[i] = reinterpret_cast<const float4*>(x)[i];
}

// ==========================================================================
// tf32 tensor-core grouped GEMMs, cp.async double-buffered.
// Tile 128x128x32, 256 threads = 8 warps (2m x 4n), warp tile 64x32.
// k-permutation trick: logical k-slot qc <-> physical k 2qc, and
// qc+4 <-> 2qc+1, applied to BOTH A and B fragments (sum over k invariant)
// -> each A fragment pair is an adjacent float2 (one LDS.64 each).
// A smem [128][40]; B smem [32][132]. B loader: 8 threads/row x 4 chunks
// (full 128 columns -- the R5 bug was loading only 1 chunk).
// ==========================================================================

// -------------------- GEMM1: h = gelu(Xg @ W1[e] + b1[e]) -----------------
__global__ __launch_bounds__(256) void gemm1_k(const float* __restrict__ x,
                                               const float* __restrict__ W1,
                                               const float* __restrict__ b1) {
    int e  = blockIdx.x >> 6;
    int mt = blockIdx.x & 63;
    int rows = g_count[e];
    int m0 = mt * 128;
    if (m0 >= rows) return;
    int base = g_offset[e];
    int n0 = blockIdx.y * 128;

    extern __shared__ float sm[];
    int tid = threadIdx.x;

    // ---- A loader: 2 threads per row, 4x16B chunks each ----
    int arow = tid >> 1;
    int akb  = (tid & 1) * 16;
    bool av  = (m0 + arow) < rows;
    int atok = av ? g_row_token[base + m0 + arow] : 0;
    const float* agp = x + (size_t)atok * Dq + akb;
    int asz = av ? 16 : 0;
    uint32_t a_sm = (uint32_t)__cvta_generic_to_shared(sm + arow * AS_STRIDE + akb);

    // ---- B loader: 8 threads per k-row, 4x16B chunks each (full 128 cols) --
    int bkr = tid >> 3;
    int bnb = (tid & 7) * 16;
    const float* w1e = W1 + (size_t)e * Dq * Hq;
    const float* bgp = w1e + (size_t)bkr * Hq + n0 + bnb;
    uint32_t b_sm = (uint32_t)__cvta_generic_to_shared(sm + A_STAGE_F + bkr * BS_STRIDE + bnb);

    // ---- compute indexing ----
    int warp = tid >> 5, lane = tid & 31;
    int wm = (warp >> 2) * 64, wn = (warp & 3) * 32;
    int qr = lane >> 2, qc = lane & 3;

    float acc[4][4][4];
    #pragma unroll
    for (int mi = 0; mi < 4; mi++)
        #pragma unroll
        for (int ni = 0; ni < 4; ni++)
            #pragma unroll
            for (int j = 0; j < 4; j++) acc[mi][ni][j] = 0.f;

    // prefetch stage 0
    #pragma unroll
    for (int c = 0; c < 4; c++) {
        cp16(a_sm + c * 16, agp + c * 4, asz);
        cp16(b_sm + c * 16, bgp + c * 4, 16);
    }
    CP_COMMIT();

    const int NKT = Dq / KT;
    for (int kt = 0; kt < NKT; kt++) {
        CP_WAIT0();
        __syncthreads();
        int cur = kt & 1;
        if (kt + 1 < NKT) {
            int nxt = cur ^ 1;
            uint32_t ao = a_sm + nxt * (STAGE_F * 4);
            uint32_t bo = b_sm + nxt * (STAGE_F * 4);
            const float* ag = agp + (kt + 1) * KT;
            const float* bg = bgp + (size_t)(kt + 1) * KT * Hq;
            #pragma unroll
            for (int c = 0; c < 4; c++) {
                cp16(ao + c * 16, ag + c * 4, asz);
                cp16(bo + c * 16, bg + c * 4, 16);
            }
            CP_COMMIT();
        }
        const float* As = sm + cur * STAGE_F;
        const float* Bs = As + A_STAGE_F;
        #pragma unroll
        for (int ks = 0; ks < KT; ks += 8) {
            float2 pa[4][2];
            float bf0[4], bf1[4];
            #pragma unroll
            for (int mi = 0; mi < 4; mi++) {
                int mb = wm + mi * 16 + qr;
                pa[mi][0] = *(const float2*)(As + mb * AS_STRIDE + ks + 2 * qc);
                pa[mi][1] = *(const float2*)(As + (mb + 8) * AS_STRIDE + ks + 2 * qc);
            }
            #pragma unroll
            for (int ni = 0; ni < 4; ni++) {
                int nb = wn + ni * 8 + qr;
                bf0[ni] = Bs[(ks + 2 * qc)     * BS_STRIDE + nb];
                bf1[ni] = Bs[(ks + 2 * qc + 1) * BS_STRIDE + nb];
            }
            #pragma unroll
            for (int mi = 0; mi < 4; mi++)
                #pragma unroll
                for (int ni = 0; ni < 4; ni++)
                    mma8(acc[mi][ni],
                         __float_as_uint(pa[mi][0].x), __float_as_uint(pa[mi][1].x),
                         __float_as_uint(pa[mi][0].y), __float_as_uint(pa[mi][1].y),
                         __float_as_uint(bf0[ni]),     __float_as_uint(bf1[ni]));
        }
        __syncthreads();
    }

    // epilogue: bias + exact gelu -> g_h
    #pragma unroll
    for (int mi = 0; mi < 4; mi++) {
        #pragma unroll
        for (int h = 0; h < 2; h++) {
            int r = wm + mi * 16 + qr + h * 8;
            if (m0 + r < rows) {
                size_t gr = (size_t)(base + m0 + r);
                float* hrow = g_h + gr * Hq;
                #pragma unroll
                for (int ni = 0; ni < 4; ni++) {
                    int c = n0 + wn + ni * 8 + qc * 2;
                    float u = acc[mi][ni][h*2+0] + b1[e * Hq + c];
                    float v = acc[mi][ni][h*2+1] + b1[e * Hq + c + 1];
                    hrow[c]     = gelu_exact(u);
                    hrow[c + 1] = gelu_exact(v);
                }
            }
        }
    }
}

// -------------------- GEMM2: z += gate * (H @ W2[e] + b2[e]) --------------
__global__ __launch_bounds__(256) void gemm2_k(const float* __restrict__ W2,
                                               const float* __restrict__ b2) {
    int e  = blockIdx.x >> 6;
    int mt = blockIdx.x & 63;
    int rows = g_count[e];
    int m0 = mt * 128;
    if (m0 >= rows) return;
    int base = g_offset[e];
    int n0 = blockIdx.y * 128;

    extern __shared__ float sm[];
    int tid = threadIdx.x;

    int arow = tid >> 1;
    int akb  = (tid & 1) * 16;
    bool av  = (m0 + arow) < rows;
    const float* agp = g_h + (size_t)(base + m0 + (av ? arow : 0)) * Hq + akb;
    int asz = av ? 16 : 0;
    uint32_t a_sm = (uint32_t)__cvta_generic_to_shared(sm + arow * AS_STRIDE + akb);

    int bkr = tid >> 3;
    int bnb = (tid & 7) * 16;
    const float* w2e = W2 + (size_t)e * Hq * Dq;
    const float* bgp = w2e + (size_t)bkr * Dq + n0 + bnb;
    uint32_t b_sm = (uint32_t)__cvta_generic_to_shared(sm + A_STAGE_F + bkr * BS_STRIDE + bnb);

    int warp = tid >> 5, lane = tid & 31;
    int wm = (warp >> 2) * 64, wn = (warp & 3) * 32;
    int qr = lane >> 2, qc = lane & 3;

    float acc[4][4][4];
    #pragma unroll
    for (int mi = 0; mi < 4; mi++)
        #pragma unroll
        for (int ni = 0; ni < 4; ni++)
            #pragma unroll
            for (int j = 0; j < 4; j++) acc[mi][ni][j] = 0.f;

    #pragma unroll
    for (int c = 0; c < 4; c++) {
        cp16(a_sm + c * 16, agp + c * 4, asz);
        cp16(b_sm + c * 16, bgp + c * 4, 16);
    }
    CP_COMMIT();

    const int NKT = Hq / KT;
    for (int kt = 0; kt < NKT; kt++) {
        CP_WAIT0();
        __syncthreads();
        int cur = kt & 1;
        if (kt + 1 < NKT) {
            int nxt = cur ^ 1;
            uint32_t ao = a_sm + nxt * (STAGE_F * 4);
            uint32_t bo = b_sm + nxt * (STAGE_F * 4);
            const float* ag = agp + (kt + 1) * KT;
            const float* bg = bgp + (size_t)(kt + 1) * KT * Dq;
            #pragma unroll
            for (int c = 0; c < 4; c++) {
                cp16(ao + c * 16, ag + c * 4, asz);
                cp16(bo + c * 16, bg + c * 4, 16);
            }
            CP_COMMIT();
        }
        const float* As = sm + cur * STAGE_F;
        const float* Bs = As + A_STAGE_F;
        #pragma unroll
        for (int ks = 0; ks < KT; ks += 8) {
            float2 pa[4][2];
            float bf0[4], bf1[4];
            #pragma unroll
            for (int mi = 0; mi < 4; mi++) {
                int mb = wm + mi * 16 + qr;
                pa[mi][0] = *(const float2*)(As + mb * AS_STRIDE + ks + 2 * qc);
                pa[mi][1] = *(const float2*)(As + (mb + 8) * AS_STRIDE + ks + 2 * qc);
            }
            #pragma unroll
            for (int ni = 0; ni < 4; ni++) {
                int nb = wn + ni * 8 + qr;
                bf0[ni] = Bs[(ks + 2 * qc)     * BS_STRIDE + nb];
                bf1[ni] = Bs[(ks + 2 * qc + 1) * BS_STRIDE + nb];
            }
            #pragma unroll
            for (int mi = 0; mi < 4; mi++)
                #pragma unroll
                for (int ni = 0; ni < 4; ni++)
                    mma8(acc[mi][ni],
                         __float_as_uint(pa[mi][0].x), __float_as_uint(pa[mi][1].x),
                         __float_as_uint(pa[mi][0].y), __float_as_uint(pa[mi][1].y),
                         __float_as_uint(bf0[ni]),     __float_as_uint(bf1[ni]));
        }
        __syncthreads();
    }

    // epilogue: gate * (acc + b2) scattered into residual accumulator
    #pragma unroll
    for (int mi = 0; mi < 4; mi++) {
        #pragma unroll
        for (int h = 0; h < 2; h++) {
            int r = wm + mi * 16 + qr + h * 8;
            if (m0 + r < rows) {
                int gr = base + m0 + r;
                int tok  = g_row_token[gr];
                float gt = g_row_gate[gr];
                float* zr = g_z + (size_t)tok * Dq;
                #pragma unroll
                for (int ni = 0; ni < 4; ni++) {
                    int c = n0 + wn + ni * 8 + qc * 2;
                    atomicAdd(&zr[c],     gt * (acc[mi][ni][h*2+0] + b2[e * Dq + c]));
                    atomicAdd(&zr[c + 1], gt * (acc[mi][ni][h*2+1] + b2[e * Dq + c + 1]));
                }
            }
        }
    }
}

// -------------------- layernorm: one block (256 thr) per token ------------
__global__ void ln_k(const float* __restrict__ gamma,
                     const float* __restrict__ beta,
                     float* __restrict__ out) {
    int t = blockIdx.x;
    int tid = threadIdx.x;
    const float4* zr = reinterpret_cast<const float4*>(g_z + (size_t)t * Dq);
    float4 v = zr[tid];
    float s  = v.x + v.y + v.z + v.w;
    float ss = v.x*v.x + v.y*v.y + v.z*v.z + v.w*v.w;

    #pragma unroll
    for (int o = 16; o > 0; o >>= 1) {
        s  += __shfl_down_sync(0xffffffffu, s, o);
        ss += __shfl_down_sync(0xffffffffu, ss, o);
    }
    __shared__ float rs[8], rss[8];
    int warp = tid >> 5, lane = tid & 31;
    if (lane == 0) { rs[warp] = s; rss[warp] = ss; }
    __syncthreads();
    if (warp == 0) {
        float a = (lane < 8) ? rs[lane] : 0.f;
        float b = (lane < 8) ? rss[lane] : 0.f;
        #pragma unroll
        for (int o = 4; o > 0; o >>= 1) {
            a += __shfl_down_sync(0xffffffffu, a, o);
            b += __shfl_down_sync(0xffffffffu, b, o);
        }
        if (lane == 0) { rs[0] = a; rss[0] = b; }
    }
    __syncthreads();
    float mu  = rs[0] * (1.f / Dq);
    float var = rss[0] * (1.f / Dq) - mu * mu;
    float rstd = rsqrtf(var + 1e-5f);

    float4 g = reinterpret_cast<const float4*>(gamma)[tid];
    float4 bta = reinterpret_cast<const float4*>(beta)[tid];
    float4 o4;
    o4.x = (v.x - mu) * rstd * g.x + bta.x;
    o4.y = (v.y - mu) * rstd * g.y + bta.y;
    o4.z = (v.z - mu) * rstd * g.z + bta.z;
    o4.w = (v.w - mu) * rstd * g.w + bta.w;
    reinterpret_cast<float4*>(out + (size_t)t * Dq)[tid] = o4;
}

// -------------------- launch ----------------------------------------------
extern "C" void kernel_launch(void* const* d_in, const int* in_sizes, int n_in,
                              void* d_out, int out_size) {
    const float* x     = (const float*)d_in[0];
    const float* gw    = (const float*)d_in[1];
    const float* gb    = (const float*)d_in[2];
    const float* W1    = (const float*)d_in[3];
    const float* b1    = (const float*)d_in[4];
    const float* W2    = (const float*)d_in[5];
    const float* b2    = (const float*)d_in[6];
    const float* gamma = (const float*)d_in[7];
    const float* beta  = (const float*)d_in[8];
    float* out = (float*)d_out;

    static bool attr_set = false;
    if (!attr_set) {
        cudaFuncSetAttribute(gemm1_k, cudaFuncAttributeMaxDynamicSharedMemorySize, SMEM_BYTES);
        cudaFuncSetAttribute(gemm2_k, cudaFuncAttributeMaxDynamicSharedMemorySize, SMEM_BYTES);
        attr_set = true;
    }

    init_k<<<1, 32>>>();
    router_k<<<Nq / 8, 256>>>(x, gw, gb);
    finalize_k<<<1, 32>>>(out + (size_t)Nq * Dq);
    scatter_k<<<Nq / 256, 256>>>();
    zinit_k<<<(Nq * Dq / 4) / 256, 256>>>(x);
    gemm1_k<<<dim3(Eq * MTILES, Hq / 128), 256, SMEM_BYTES>>>(x, W1, b1);
    gemm2_k<<<dim3(Eq * MTILES, Dq / 128), 256, SMEM_BYTES>>>(W2, b2);
    ln_k<<<Nq, 256>>>(gamma, beta, out);
    (void)in_sizes; (void)n_in; (void)out_size;
}

// round 12
// speedup vs baseline: 3.5630x; 3.5630x over previous
#include <cuda_runtime.h>
#include <cuda_fp16.h>
#include <math.h>
#include <stdint.h>

// Problem dims (fixed by the dataset)
#define Bq 4
#define Tq 2048
#define Dq 1024
#define Hq 2048
#define Eq 8
#define Kq 2
#define Nq (Bq*Tq)          // 8192 tokens
#define NROWS (Nq*Kq)       // 16384 (token, expert) pairs
#define MTILES 64           // worst case: one expert gets all 8192 tokens

// GEMM tiling (fp16 path)
#define KT 32                    // k-tile in halfs
#define A_ROW_B 80               // A smem row stride bytes (64B data + 16B pad)
#define B_ROW_B 272              // B smem row stride bytes (256B data + 16B pad)
#define A_STAGE_BYTES (128*A_ROW_B)   // 10240
#define B_STAGE_BYTES (KT*B_ROW_B)    // 8704
#define STAGE_BYTES (A_STAGE_BYTES+B_STAGE_BYTES)  // 18944
#define SMEM_BYTES (2*STAGE_BYTES)                 // 37888

// -------------------- scratch (device globals; no allocation allowed) ------
__device__ int    g_count[Eq];
__device__ int    g_offset[Eq];
__device__ int    g_cursor[Eq];
__device__ float  g_imp_sum[Eq];
__device__ float  g_ent_sum;
__device__ int    g_tk_idx[Nq*Kq];
__device__ float  g_tk_gate[Nq*Kq];
__device__ int    g_row_token[NROWS];
__device__ float  g_row_gate[NROWS];
__device__ __half g_xh[(size_t)Nq*Dq];      // x in fp16                (16 MB)
__device__ __half g_w1h[(size_t)Eq*Dq*Hq]; // W1 in fp16 [E][D][H]     (32 MB)
__device__ __half g_w2h[(size_t)Eq*Hq*Dq]; // W2 in fp16 [E][H][D]     (32 MB)
__device__ __half g_h[(size_t)NROWS*Hq];   // gelu intermediate fp16   (64 MB)
__device__ float  g_z[(size_t)Nq*Dq];      // residual accumulator (x + moe_out)

// -------------------- helpers ---------------------------------------------
__device__ __forceinline__ void mma16(float* d,
                                      uint32_t a0, uint32_t a1, uint32_t a2, uint32_t a3,
                                      uint32_t b0, uint32_t b1) {
    asm volatile("mma.sync.aligned.m16n8k16.row.col.f32.f16.f16.f32 "
                 "{%0,%1,%2,%3}, {%4,%5,%6,%7}, {%8,%9}, {%0,%1,%2,%3};"
                 : "+f"(d[0]), "+f"(d[1]), "+f"(d[2]), "+f"(d[3])
                 : "r"(a0), "r"(a1), "r"(a2), "r"(a3), "r"(b0), "r"(b1));
}

#define LDSM_X4(r0, r1, r2, r3, addr) \
    asm volatile("ldmatrix.sync.aligned.m8n8.x4.shared.b16 {%0,%1,%2,%3}, [%4];" \
                 : "=r"(r0), "=r"(r1), "=r"(r2), "=r"(r3) : "r"(addr))

#define LDSM_X4_T(r0, r1, r2, r3, addr) \
    asm volatile("ldmatrix.sync.aligned.m8n8.x4.trans.shared.b16 {%0,%1,%2,%3}, [%4];" \
                 : "=r"(r0), "=r"(r1), "=r"(r2), "=r"(r3) : "r"(addr))

__device__ __forceinline__ void cp16(uint32_t dst, const void* src, int szr) {
    asm volatile("cp.async.cg.shared.global [%0], [%1], 16, %2;"
                 :: "r"(dst), "l"(src), "r"(szr));
}
#define CP_COMMIT() asm volatile("cp.async.commit_group;")
#define CP_WAIT0()  asm volatile("cp.async.wait_group 0;")

__device__ __forceinline__ float gelu_exact(float c) {
    return 0.5f * c * (1.f + erff(c * 0.70710678118654752f));
}

__device__ __forceinline__ uint32_t h2u(__half2 h) {
    return *reinterpret_cast<uint32_t*>(&h);
}

// -------------------- fp32 -> fp16 conversion (8 elems/thread) ------------
__global__ void cvt_k(const float4* __restrict__ in, uint4* __restrict__ out) {
    size_t i = (size_t)blockIdx.x * blockDim.x + threadIdx.x;
    float4 f0 = in[2*i], f1 = in[2*i+1];
    uint4 o;
    o.x = h2u(__floats2half2_rn(f0.x, f0.y));
    o.y = h2u(__floats2half2_rn(f0.z, f0.w));
    o.z = h2u(__floats2half2_rn(f1.x, f1.y));
    o.w = h2u(__floats2half2_rn(f1.z, f1.w));
    out[i] = o;
}

// -------------------- init ------------------------------------------------
__global__ void init_k() {
    int i = threadIdx.x;
    if (i < Eq) { g_count[i] = 0; g_imp_sum[i] = 0.f; }
    if (i == Eq) g_ent_sum = 0.f;
}

// -------------------- router: one warp per token --------------------------
__global__ void router_k(const float* __restrict__ x,
                         const float* __restrict__ gw,
                         const float* __restrict__ gb) {
    __shared__ float s_imp[Eq];
    __shared__ int   s_cnt[Eq];
    __shared__ float s_ent;
    int tid = threadIdx.x;
    if (tid < Eq) { s_imp[tid] = 0.f; s_cnt[tid] = 0; }
    if (tid == Eq) s_ent = 0.f;
    __syncthreads();

    int warp = tid >> 5, lane = tid & 31;
    int t = blockIdx.x * 8 + warp;

    float acc[Eq];
    #pragma unroll
    for (int e = 0; e < Eq; e++) acc[e] = 0.f;

    const float* xr = x + (size_t)t * Dq;
    for (int d = lane; d < Dq; d += 32) {
        float xv = xr[d];
        const float* gwr = gw + d * Eq;
        #pragma unroll
        for (int e = 0; e < Eq; e++) acc[e] += xv * gwr[e];
    }
    #pragma unroll
    for (int e = 0; e < Eq; e++) {
        #pragma unroll
        for (int o = 16; o > 0; o >>= 1)
            acc[e] += __shfl_down_sync(0xffffffffu, acc[e], o);
    }

    if (lane == 0) {
        float lg[Eq], p[Eq];
        float mx = -1e30f;
        #pragma unroll
        for (int e = 0; e < Eq; e++) { lg[e] = acc[e] + gb[e]; mx = fmaxf(mx, lg[e]); }
        float se = 0.f;
        #pragma unroll
        for (int e = 0; e < Eq; e++) { p[e] = expf(lg[e] - mx); se += p[e]; }
        float inv = 1.f / se;
        float ent = 0.f;
        #pragma unroll
        for (int e = 0; e < Eq; e++) {
            p[e] *= inv;
            ent -= p[e] * logf(p[e] + 1e-8f);
            atomicAdd(&s_imp[e], p[e]);
        }
        float bv = -1e30f, sv = -1e30f; int bi = 0, si = 0;
        #pragma unroll
        for (int e = 0; e < Eq; e++) {
            float v = lg[e];
            if (v > bv) { sv = bv; si = bi; bv = v; bi = e; }
            else if (v > sv) { sv = v; si = e; }
        }
        float g0 = 1.f / (1.f + expf(sv - bv));
        float g1 = 1.f - g0;
        g_tk_idx[2*t]   = bi;  g_tk_idx[2*t+1]  = si;
        g_tk_gate[2*t]  = g0;  g_tk_gate[2*t+1] = g1;
        atomicAdd(&s_cnt[bi], 1);
        atomicAdd(&s_cnt[si], 1);
        atomicAdd(&s_ent, ent);
    }
    __syncthreads();
    if (tid < Eq) {
        if (s_cnt[tid]) atomicAdd(&g_count[tid], s_cnt[tid]);
        atomicAdd(&g_imp_sum[tid], s_imp[tid]);
    }
    if (tid == Eq) atomicAdd(&g_ent_sum, s_ent);
}

// -------------------- finalize scalars + prefix offsets -------------------
__global__ void finalize_k(float* __restrict__ out_tail) {
    if (threadIdx.x != 0) return;
    int c = 0;
    #pragma unroll
    for (int e = 0; e < Eq; e++) { g_offset[e] = c; g_cursor[e] = c; c += g_count[e]; }
    float invN = 1.f / (float)Nq;
    float bal = 0.f, ue = 0.f;
    #pragma unroll
    for (int e = 0; e < Eq; e++) {
        float imp  = g_imp_sum[e] * invN;
        float load = (float)g_count[e] * invN;
        bal += imp * load;
        ue  -= load * logf(load + 1e-8f);
        out_tail[3 + e]  = load;
        out_tail[11 + e] = imp;
    }
    out_tail[0] = (float)Eq * bal;
    out_tail[1] = g_ent_sum * invN;
    out_tail[2] = ue;
}

// -------------------- scatter: compact per-expert row lists ---------------
__global__ void scatter_k() {
    int t = blockIdx.x * blockDim.x + threadIdx.x;
    if (t >= Nq) return;
    #pragma unroll
    for (int k = 0; k < Kq; k++) {
        int e = g_tk_idx[2*t + k];
        int pos = atomicAdd(&g_cursor[e], 1);
        g_row_token[pos] = t;
        g_row_gate[pos]  = g_tk_gate[2*t + k];
    }
}

// -------------------- z = x (residual init) -------------------------------
__global__ void zinit_k(const float* __restrict__ x) {
    size_t i = (size_t)blockIdx.x * blockDim.x + threadIdx.x;
    reinterpret_cast<float4*>(g_z)[i] = reinterpret_cast<const float4*>(x)[i];
}

// ==========================================================================
// fp16 tensor-core grouped GEMMs, cp.async double-buffered, ldmatrix-fed.
// Tile 128x128x32(halfs), 256 threads = 8 warps (2m x 4n), warp tile 64x32.
// mma.m16n8k16.f16 (2048 MAC/instr, 2x tf32 rate), fp32 accumulate.
// A smem [128 rows][80 B] (row*80 mod 128 spans all eight 16B slots:
//   conflict-free LDSM). B smem [32 k-rows][272 B] (k*272 mod 128 = k*16:
//   conflict-free LDSM.trans).
// Per warp per k-tile: 12 LDSM + 32 MMA (vs 96 LDS + 64 MMA on tf32 path).
// ==========================================================================

// -------------------- GEMM1: h = gelu(Xg @ W1[e] + b1[e]) -----------------
__global__ __launch_bounds__(256) void gemm1_k(const __half* __restrict__ b1_dummy,
                                               const float* __restrict__ b1) {
    int e  = blockIdx.x >> 6;
    int mt = blockIdx.x & 63;
    int rows = g_count[e];
    int m0 = mt * 128;
    if (m0 >= rows) return;
    int base = g_offset[e];
    int n0 = blockIdx.y * 128;

    extern __shared__ __align__(16) char smraw[];
    uint32_t sm0 = (uint32_t)__cvta_generic_to_shared(smraw);
    int tid = threadIdx.x;

    // ---- A loader: 2 threads per row, 2x16B chunks each (64B/row) ----
    int arow = tid >> 1;
    int akb  = (tid & 1) * 16;                 // half offset
    bool av  = (m0 + arow) < rows;
    int atok = av ? g_row_token[base + m0 + arow] : 0;
    const __half* agp = g_xh + (size_t)atok * Dq + akb;
    int asz = av ? 16 : 0;
    uint32_t a_sm = sm0 + arow * A_ROW_B + (tid & 1) * 32;

    // ---- B loader: 8 threads per k-row, 2x16B chunks each (256B/row) ----
    int bkr = tid >> 3;
    int bnb = (tid & 7) * 16;                  // half offset
    const __half* bgp = g_w1h + (size_t)e * Dq * Hq + (size_t)bkr * Hq + n0 + bnb;
    uint32_t b_sm = sm0 + A_STAGE_BYTES + bkr * B_ROW_B + bnb * 2;

    // ---- compute indexing ----
    int warp = tid >> 5, lane = tid & 31;
    int wm = (warp >> 2) * 64, wn = (warp & 3) * 32;
    int qr = lane >> 2, qc = lane & 3;
    uint32_t a_lm_off = (uint32_t)((wm + (lane & 15)) * A_ROW_B + (lane >> 4) * 16);
    uint32_t b_lm_off = (uint32_t)(A_STAGE_BYTES + (lane & 15) * B_ROW_B
                                   + (wn + (lane >> 4) * 8) * 2);

    float acc[4][4][4];
    #pragma unroll
    for (int mi = 0; mi < 4; mi++)
        #pragma unroll
        for (int ni = 0; ni < 4; ni++)
            #pragma unroll
            for (int j = 0; j < 4; j++) acc[mi][ni][j] = 0.f;

    // prefetch stage 0
    #pragma unroll
    for (int c = 0; c < 2; c++) {
        cp16(a_sm + c * 16, agp + c * 8, asz);
        cp16(b_sm + c * 16, bgp + c * 8, 16);
    }
    CP_COMMIT();

    const int NKT = Dq / KT;   // 32
    for (int kt = 0; kt < NKT; kt++) {
        CP_WAIT0();
        __syncthreads();
        int cur = kt & 1;
        if (kt + 1 < NKT) {
            int nxt = cur ^ 1;
            uint32_t ao = a_sm + nxt * STAGE_BYTES;
            uint32_t bo = b_sm + nxt * STAGE_BYTES;
            const __half* ag = agp + (kt + 1) * KT;
            const __half* bg = bgp + (size_t)(kt + 1) * KT * Hq;
            #pragma unroll
            for (int c = 0; c < 2; c++) {
                cp16(ao + c * 16, ag + c * 8, asz);
                cp16(bo + c * 16, bg + c * 8, 16);
            }
            CP_COMMIT();
        }
        uint32_t sbase = sm0 + cur * STAGE_BYTES;
        uint32_t a_lm = sbase + a_lm_off;
        uint32_t b_lm = sbase + b_lm_off;
        #pragma unroll
        for (int ks8 = 0; ks8 < 2; ks8++) {   // two k16 steps per k-tile
            uint32_t af[4][4], bf[4][2];
            #pragma unroll
            for (int mi = 0; mi < 4; mi++)
                LDSM_X4(af[mi][0], af[mi][1], af[mi][2], af[mi][3],
                        a_lm + mi * (16 * A_ROW_B) + ks8 * 32);
            #pragma unroll
            for (int n2 = 0; n2 < 2; n2++)
                LDSM_X4_T(bf[2*n2][0], bf[2*n2][1], bf[2*n2+1][0], bf[2*n2+1][1],
                          b_lm + n2 * 32 + ks8 * (16 * B_ROW_B));
            #pragma unroll
            for (int mi = 0; mi < 4; mi++)
                #pragma unroll
                for (int ni = 0; ni < 4; ni++)
                    mma16(acc[mi][ni], af[mi][0], af[mi][1], af[mi][2], af[mi][3],
                          bf[ni][0], bf[ni][1]);
        }
        __syncthreads();
    }

    // epilogue: bias + exact gelu -> g_h (fp16)
    #pragma unroll
    for (int mi = 0; mi < 4; mi++) {
        #pragma unroll
        for (int h = 0; h < 2; h++) {
            int r = wm + mi * 16 + qr + h * 8;
            if (m0 + r < rows) {
                size_t gr = (size_t)(base + m0 + r);
                __half* hrow = g_h + gr * Hq;
                #pragma unroll
                for (int ni = 0; ni < 4; ni++) {
                    int c = n0 + wn + ni * 8 + qc * 2;
                    float u = acc[mi][ni][h*2+0] + b1[e * Hq + c];
                    float v = acc[mi][ni][h*2+1] + b1[e * Hq + c + 1];
                    *reinterpret_cast<__half2*>(hrow + c) =
                        __floats2half2_rn(gelu_exact(u), gelu_exact(v));
                }
            }
        }
    }
    (void)b1_dummy;
}

// -------------------- GEMM2: z += gate * (H @ W2[e] + b2[e]) --------------
__global__ __launch_bounds__(256) void gemm2_k(const float* __restrict__ b2) {
    int e  = blockIdx.x >> 6;
    int mt = blockIdx.x & 63;
    int rows = g_count[e];
    int m0 = mt * 128;
    if (m0 >= rows) return;
    int base = g_offset[e];
    int n0 = blockIdx.y * 128;

    extern __shared__ __align__(16) char smraw[];
    uint32_t sm0 = (uint32_t)__cvta_generic_to_shared(smraw);
    int tid = threadIdx.x;

    int arow = tid >> 1;
    int akb  = (tid & 1) * 16;
    bool av  = (m0 + arow) < rows;
    const __half* agp = g_h + (size_t)(base + m0 + (av ? arow : 0)) * Hq + akb;
    int asz = av ? 16 : 0;
    uint32_t a_sm = sm0 + arow * A_ROW_B + (tid & 1) * 32;

    int bkr = tid >> 3;
    int bnb = (tid & 7) * 16;
    const __half* bgp = g_w2h + (size_t)e * Hq * Dq + (size_t)bkr * Dq + n0 + bnb;
    uint32_t b_sm = sm0 + A_STAGE_BYTES + bkr * B_ROW_B + bnb * 2;

    int warp = tid >> 5, lane = tid & 31;
    int wm = (warp >> 2) * 64, wn = (warp & 3) * 32;
    int qr = lane >> 2, qc = lane & 3;
    uint32_t a_lm_off = (uint32_t)((wm + (lane & 15)) * A_ROW_B + (lane >> 4) * 16);
    uint32_t b_lm_off = (uint32_t)(A_STAGE_BYTES + (lane & 15) * B_ROW_B
                                   + (wn + (lane >> 4) * 8) * 2);

    float acc[4][4][4];
    #pragma unroll
    for (int mi = 0; mi < 4; mi++)
        #pragma unroll
        for (int ni = 0; ni < 4; ni++)
            #pragma unroll
            for (int j = 0; j < 4; j++) acc[mi][ni][j] = 0.f;

    #pragma unroll
    for (int c = 0; c < 2; c++) {
        cp16(a_sm + c * 16, agp + c * 8, asz);
        cp16(b_sm + c * 16, bgp + c * 8, 16);
    }
    CP_COMMIT();

    const int NKT = Hq / KT;   // 64
    for (int kt = 0; kt < NKT; kt++) {
        CP_WAIT0();
        __syncthreads();
        int cur = kt & 1;
        if (kt + 1 < NKT) {
            int nxt = cur ^ 1;
            uint32_t ao = a_sm + nxt * STAGE_BYTES;
            uint32_t bo = b_sm + nxt * STAGE_BYTES;
            const __half* ag = agp + (kt + 1) * KT;
            const __half* bg = bgp + (size_t)(kt + 1) * KT * Dq;
            #pragma unroll
            for (int c = 0; c < 2; c++) {
                cp16(ao + c * 16, ag + c * 8, asz);
                cp16(bo + c * 16, bg + c * 8, 16);
            }
            CP_COMMIT();
        }
        uint32_t sbase = sm0 + cur * STAGE_BYTES;
        uint32_t a_lm = sbase + a_lm_off;
        uint32_t b_lm = sbase + b_lm_off;
        #pragma unroll
        for (int ks8 = 0; ks8 < 2; ks8++) {
            uint32_t af[4][4], bf[4][2];
            #pragma unroll
            for (int mi = 0; mi < 4; mi++)
                LDSM_X4(af[mi][0], af[mi][1], af[mi][2], af[mi][3],
                        a_lm + mi * (16 * A_ROW_B) + ks8 * 32);
            #pragma unroll
            for (int n2 = 0; n2 < 2; n2++)
                LDSM_X4_T(bf[2*n2][0], bf[2*n2][1], bf[2*n2+1][0], bf[2*n2+1][1],
                          b_lm + n2 * 32 + ks8 * (16 * B_ROW_B));
            #pragma unroll
            for (int mi = 0; mi < 4; mi++)
                #pragma unroll
                for (int ni = 0; ni < 4; ni++)
                    mma16(acc[mi][ni], af[mi][0], af[mi][1], af[mi][2], af[mi][3],
                          bf[ni][0], bf[ni][1]);
        }
        __syncthreads();
    }

    // epilogue: gate * (acc + b2) scattered into residual accumulator
    #pragma unroll
    for (int mi = 0; mi < 4; mi++) {
        #pragma unroll
        for (int h = 0; h < 2; h++) {
            int r = wm + mi * 16 + qr + h * 8;
            if (m0 + r < rows) {
                int gr = base + m0 + r;
                int tok  = g_row_token[gr];
                float gt = g_row_gate[gr];
                float* zr = g_z + (size_t)tok * Dq;
                #pragma unroll
                for (int ni = 0; ni < 4; ni++) {
                    int c = n0 + wn + ni * 8 + qc * 2;
                    atomicAdd(&zr[c],     gt * (acc[mi][ni][h*2+0] + b2[e * Dq + c]));
                    atomicAdd(&zr[c + 1], gt * (acc[mi][ni][h*2+1] + b2[e * Dq + c + 1]));
                }
            }
        }
    }
}

// -------------------- layernorm: one block (256 thr) per token ------------
__global__ void ln_k(const float* __restrict__ gamma,
                     const float* __restrict__ beta,
                     float* __restrict__ out) {
    int t = blockIdx.x;
    int tid = threadIdx.x;
    const float4* zr = reinterpret_cast<const float4*>(g_z + (size_t)t * Dq);
    float4 v = zr[tid];
    float s  = v.x + v.y + v.z + v.w;
    float ss = v.x*v.x + v.y*v.y + v.z*v.z + v.w*v.w;

    #pragma unroll
    for (int o = 16; o > 0; o >>= 1) {
        s  += __shfl_down_sync(0xffffffffu, s, o);
        ss += __shfl_down_sync(0xffffffffu, ss, o);
    }
    __shared__ float rs[8], rss[8];
    int warp = tid >> 5, lane = tid & 31;
    if (lane == 0) { rs[warp] = s; rss[warp] = ss; }
    __syncthreads();
    if (warp == 0) {
        float a = (lane < 8) ? rs[lane] : 0.f;
        float b = (lane < 8) ? rss[lane] : 0.f;
        #pragma unroll
        for (int o = 4; o > 0; o >>= 1) {
            a += __shfl_down_sync(0xffffffffu, a, o);
            b += __shfl_down_sync(0xffffffffu, b, o);
        }
        if (lane == 0) { rs[0] = a; rss[0] = b; }
    }
    __syncthreads();
    float mu  = rs[0] * (1.f / Dq);
    float var = rss[0] * (1.f / Dq) - mu * mu;
    float rstd = rsqrtf(var + 1e-5f);

    float4 g = reinterpret_cast<const float4*>(gamma)[tid];
    float4 bta = reinterpret_cast<const float4*>(beta)[tid];
    float4 o4;
    o4.x = (v.x - mu) * rstd * g.x + bta.x;
    o4.y = (v.y - mu) * rstd * g.y + bta.y;
    o4.z = (v.z - mu) * rstd * g.z + bta.z;
    o4.w = (v.w - mu) * rstd * g.w + bta.w;
    reinterpret_cast<float4*>(out + (size_t)t * Dq)[tid] = o4;
}

// -------------------- launch ----------------------------------------------
extern "C" void kernel_launch(void* const* d_in, const int* in_sizes, int n_in,
                              void* d_out, int out_size) {
    const float* x     = (const float*)d_in[0];
    const float* gw    = (const float*)d_in[1];
    const float* gb    = (const float*)d_in[2];
    const float* W1    = (const float*)d_in[3];
    const float* b1    = (const float*)d_in[4];
    const float* W2    = (const float*)d_in[5];
    const float* b2    = (const float*)d_in[6];
    const float* gamma = (const float*)d_in[7];
    const float* beta  = (const float*)d_in[8];
    float* out = (float*)d_out;

    static bool attr_set = false;
    if (!attr_set) {
        cudaFuncSetAttribute(gemm1_k, cudaFuncAttributeMaxDynamicSharedMemorySize, SMEM_BYTES);
        cudaFuncSetAttribute(gemm2_k, cudaFuncAttributeMaxDynamicSharedMemorySize, SMEM_BYTES);
        attr_set = true;
    }

    __half* xh;  cudaGetSymbolAddress((void**)&xh,  g_xh);
    __half* w1h; cudaGetSymbolAddress((void**)&w1h, g_w1h);
    __half* w2h; cudaGetSymbolAddress((void**)&w2h, g_w2h);

    // fp32 -> fp16 conversions (8 elems per thread)
    cvt_k<<<(Nq*Dq/8)/256, 256>>>((const float4*)x,  (uint4*)xh);
    cvt_k<<<((size_t)Eq*Dq*Hq/8)/256, 256>>>((const float4*)W1, (uint4*)w1h);
    cvt_k<<<((size_t)Eq*Hq*Dq/8)/256, 256>>>((const float4*)W2, (uint4*)w2h);

    init_k<<<1, 32>>>();
    router_k<<<Nq / 8, 256>>>(x, gw, gb);
    finalize_k<<<1, 32>>>(out + (size_t)Nq * Dq);
    scatter_k<<<Nq / 256, 256>>>();
    zinit_k<<<(Nq * Dq / 4) / 256, 256>>>(x);
    gemm1_k<<<dim3(Eq * MTILES, Hq / 128), 256, SMEM_BYTES>>>(nullptr, b1);
    gemm2_k<<<dim3(Eq * MTILES, Dq / 128), 256, SMEM_BYTES>>>(b2);
    ln_k<<<Nq, 256>>>(gamma, beta, out);
    (void)in_sizes; (void)n_in; (void)out_size;
}

// round 14
// speedup vs baseline: 3.8744x; 1.0874x over previous
#include <cuda_runtime.h>
#include <cuda_fp16.h>
#include <math.h>
#include <stdint.h>

// Problem dims (fixed by the dataset)
#define Bq 4
#define Tq 2048
#define Dq 1024
#define Hq 2048
#define Eq 8
#define Kq 2
#define Nq (Bq*Tq)          // 8192 tokens
#define NROWS (Nq*Kq)       // 16384 (token, expert) pairs
#define MTILES 64           // worst case: one expert gets all 8192 tokens

// GEMM tiling (fp16 path)
#define KT 32                    // k-tile in halfs
#define A_ROW_B 80               // A smem row stride bytes (64B data + 16B pad)
#define B_ROW_B 272              // B smem row stride bytes (256B data + 16B pad)
#define A_STAGE_BYTES (128*A_ROW_B)   // 10240
#define B_STAGE_BYTES (KT*B_ROW_B)    // 8704
#define STAGE_BYTES (A_STAGE_BYTES+B_STAGE_BYTES)  // 18944
#define NSTAGE 3
#define SMEM_BYTES (NSTAGE*STAGE_BYTES)            // 56832

// -------------------- scratch (device globals; no allocation allowed) ------
__device__ int    g_count[Eq];
__device__ int    g_offset[Eq];
__device__ int    g_cursor[Eq];
__device__ float  g_imp_sum[Eq];
__device__ float  g_ent_sum;
__device__ int    g_tk_idx[Nq*Kq];
__device__ float  g_tk_gate[Nq*Kq];
__device__ int    g_row_token[NROWS];
__device__ float  g_row_gate[NROWS];
__device__ __half g_xh[(size_t)Nq*Dq];      // x in fp16                (16 MB)
__device__ __half g_w1h[(size_t)Eq*Dq*Hq]; // W1 in fp16 [E][D][H]     (32 MB)
__device__ __half g_w2h[(size_t)Eq*Hq*Dq]; // W2 in fp16 [E][H][D]     (32 MB)
__device__ __half g_h[(size_t)NROWS*Hq];   // gelu intermediate fp16   (64 MB)
__device__ float  g_z[(size_t)Nq*Dq];      // residual accumulator (x + moe_out)

// -------------------- helpers ---------------------------------------------
__device__ __forceinline__ void mma16(float* d,
                                      uint32_t a0, uint32_t a1, uint32_t a2, uint32_t a3,
                                      uint32_t b0, uint32_t b1) {
    asm volatile("mma.sync.aligned.m16n8k16.row.col.f32.f16.f16.f32 "
                 "{%0,%1,%2,%3}, {%4,%5,%6,%7}, {%8,%9}, {%0,%1,%2,%3};"
                 : "+f"(d[0]), "+f"(d[1]), "+f"(d[2]), "+f"(d[3])
                 : "r"(a0), "r"(a1), "r"(a2), "r"(a3), "r"(b0), "r"(b1));
}

#define LDSM_X4(r0, r1, r2, r3, addr) \
    asm volatile("ldmatrix.sync.aligned.m8n8.x4.shared.b16 {%0,%1,%2,%3}, [%4];" \
                 : "=r"(r0), "=r"(r1), "=r"(r2), "=r"(r3) : "r"(addr))

#define LDSM_X4_T(r0, r1, r2, r3, addr) \
    asm volatile("ldmatrix.sync.aligned.m8n8.x4.trans.shared.b16 {%0,%1,%2,%3}, [%4];" \
                 : "=r"(r0), "=r"(r1), "=r"(r2), "=r"(r3) : "r"(addr))

__device__ __forceinline__ void cp16(uint32_t dst, const void* src, int szr) {
    asm volatile("cp.async.cg.shared.global [%0], [%1], 16, %2;"
                 :: "r"(dst), "l"(src), "r"(szr));
}
#define CP_COMMIT() asm volatile("cp.async.commit_group;")
#define CP_WAIT1()  asm volatile("cp.async.wait_group 1;")

__device__ __forceinline__ float gelu_exact(float c) {
    return 0.5f * c * (1.f + erff(c * 0.70710678118654752f));
}

__device__ __forceinline__ uint32_t h2u(__half2 h) {
    return *reinterpret_cast<uint32_t*>(&h);
}

// -------------------- fp32 -> fp16 conversion (8 elems/thread) ------------
__global__ void cvt_k(const float4* __restrict__ in, uint4* __restrict__ out) {
    size_t i = (size_t)blockIdx.x * blockDim.x + threadIdx.x;
    float4 f0 = in[2*i], f1 = in[2*i+1];
    uint4 o;
    o.x = h2u(__floats2half2_rn(f0.x, f0.y));
    o.y = h2u(__floats2half2_rn(f0.z, f0.w));
    o.z = h2u(__floats2half2_rn(f1.x, f1.y));
    o.w = h2u(__floats2half2_rn(f1.z, f1.w));
    out[i] = o;
}

// -------------------- init ------------------------------------------------
__global__ void init_k() {
    int i = threadIdx.x;
    if (i < Eq) { g_count[i] = 0; g_imp_sum[i] = 0.f; }
    if (i == Eq) g_ent_sum = 0.f;
}

// -------------------- router: one warp per token --------------------------
__global__ void router_k(const float* __restrict__ x,
                         const float* __restrict__ gw,
                         const float* __restrict__ gb) {
    __shared__ float s_imp[Eq];
    __shared__ int   s_cnt[Eq];
    __shared__ float s_ent;
    int tid = threadIdx.x;
    if (tid < Eq) { s_imp[tid] = 0.f; s_cnt[tid] = 0; }
    if (tid == Eq) s_ent = 0.f;
    __syncthreads();

    int warp = tid >> 5, lane = tid & 31;
    int t = blockIdx.x * 8 + warp;

    float acc[Eq];
    #pragma unroll
    for (int e = 0; e < Eq; e++) acc[e] = 0.f;

    const float* xr = x + (size_t)t * Dq;
    for (int d = lane; d < Dq; d += 32) {
        float xv = xr[d];
        const float* gwr = gw + d * Eq;
        #pragma unroll
        for (int e = 0; e < Eq; e++) acc[e] += xv * gwr[e];
    }
    #pragma unroll
    for (int e = 0; e < Eq; e++) {
        #pragma unroll
        for (int o = 16; o > 0; o >>= 1)
            acc[e] += __shfl_down_sync(0xffffffffu, acc[e], o);
    }

    if (lane == 0) {
        float lg[Eq], p[Eq];
        float mx = -1e30f;
        #pragma unroll
        for (int e = 0; e < Eq; e++) { lg[e] = acc[e] + gb[e]; mx = fmaxf(mx, lg[e]); }
        float se = 0.f;
        #pragma unroll
        for (int e = 0; e < Eq; e++) { p[e] = expf(lg[e] - mx); se += p[e]; }
        float inv = 1.f / se;
        float ent = 0.f;
        #pragma unroll
        for (int e = 0; e < Eq; e++) {
            p[e] *= inv;
            ent -= p[e] * logf(p[e] + 1e-8f);
            atomicAdd(&s_imp[e], p[e]);
        }
        float bv = -1e30f, sv = -1e30f; int bi = 0, si = 0;
        #pragma unroll
        for (int e = 0; e < Eq; e++) {
            float v = lg[e];
            if (v > bv) { sv = bv; si = bi; bv = v; bi = e; }
            else if (v > sv) { sv = v; si = e; }
        }
        float g0 = 1.f / (1.f + expf(sv - bv));
        float g1 = 1.f - g0;
        g_tk_idx[2*t]   = bi;  g_tk_idx[2*t+1]  = si;
        g_tk_gate[2*t]  = g0;  g_tk_gate[2*t+1] = g1;
        atomicAdd(&s_cnt[bi], 1);
        atomicAdd(&s_cnt[si], 1);
        atomicAdd(&s_ent, ent);
    }
    __syncthreads();
    if (tid < Eq) {
        if (s_cnt[tid]) atomicAdd(&g_count[tid], s_cnt[tid]);
        atomicAdd(&g_imp_sum[tid], s_imp[tid]);
    }
    if (tid == Eq) atomicAdd(&g_ent_sum, s_ent);
}

// -------------------- finalize scalars + prefix offsets -------------------
__global__ void finalize_k(float* __restrict__ out_tail) {
    if (threadIdx.x != 0) return;
    int c = 0;
    #pragma unroll
    for (int e = 0; e < Eq; e++) { g_offset[e] = c; g_cursor[e] = c; c += g_count[e]; }
    float invN = 1.f / (float)Nq;
    float bal = 0.f, ue = 0.f;
    #pragma unroll
    for (int e = 0; e < Eq; e++) {
        float imp  = g_imp_sum[e] * invN;
        float load = (float)g_count[e] * invN;
        bal += imp * load;
        ue  -= load * logf(load + 1e-8f);
        out_tail[3 + e]  = load;
        out_tail[11 + e] = imp;
    }
    out_tail[0] = (float)Eq * bal;
    out_tail[1] = g_ent_sum * invN;
    out_tail[2] = ue;
}

// -------------------- scatter: compact per-expert row lists ---------------
__global__ void scatter_k() {
    int t = blockIdx.x * blockDim.x + threadIdx.x;
    if (t >= Nq) return;
    #pragma unroll
    for (int k = 0; k < Kq; k++) {
        int e = g_tk_idx[2*t + k];
        int pos = atomicAdd(&g_cursor[e], 1);
        g_row_token[pos] = t;
        g_row_gate[pos]  = g_tk_gate[2*t + k];
    }
}

// -------------------- z = x (residual init) -------------------------------
__global__ void zinit_k(const float* __restrict__ x) {
    size_t i = (size_t)blockIdx.x * blockDim.x + threadIdx.x;
    reinterpret_cast<float4*>(g_z)[i] = reinterpret_cast<const float4*>(x)[i];
}

// ==========================================================================
// fp16 tensor-core grouped GEMMs, 3-stage cp.async ring, ldmatrix-fed.
// Tile 128x128x32(halfs), 256 threads = 8 warps (2m x 4n), warp tile 64x32.
// mma.m16n8k16.f16, fp32 accumulate.
// Mainloop: wait_group 1 (stage kt, committed 2 iters ago -> one full
// compute-phase of latency slack) + ONE __syncthreads per k-tile (also
// retires readers of stage kt-1 == kt+2 mod 3 before it is overwritten).
// ==========================================================================

// -------------------- GEMM1: h = gelu(Xg @ W1[e] + b1[e]) -----------------
__global__ __launch_bounds__(256, 2) void gemm1_k(const float* __restrict__ b1) {
    int e  = blockIdx.x >> 6;
    int mt = blockIdx.x & 63;
    int rows = g_count[e];
    int m0 = mt * 128;
    if (m0 >= rows) return;
    int base = g_offset[e];
    int n0 = blockIdx.y * 128;

    extern __shared__ __align__(16) char smraw[];
    uint32_t sm0 = (uint32_t)__cvta_generic_to_shared(smraw);
    int tid = threadIdx.x;

    // ---- A loader: 2 threads per row, 2x16B chunks each (64B/row) ----
    int arow = tid >> 1;
    bool av  = (m0 + arow) < rows;
    int atok = av ? g_row_token[base + m0 + arow] : 0;
    const __half* agp = g_xh + (size_t)atok * Dq + (tid & 1) * 16;
    int asz = av ? 16 : 0;
    uint32_t a_sm = sm0 + arow * A_ROW_B + (tid & 1) * 32;

    // ---- B loader: 8 threads per k-row, 2x16B chunks each (256B/row) ----
    int bkr = tid >> 3;
    int bnb = (tid & 7) * 16;
    const __half* bgp = g_w1h + (size_t)e * Dq * Hq + (size_t)bkr * Hq + n0 + bnb;
    uint32_t b_sm = sm0 + A_STAGE_BYTES + bkr * B_ROW_B + bnb * 2;

    // ---- compute indexing ----
    int warp = tid >> 5, lane = tid & 31;
    int wm = (warp >> 2) * 64, wn = (warp & 3) * 32;
    int qr = lane >> 2, qc = lane & 3;
    uint32_t a_lm_off = (uint32_t)((wm + (lane & 15)) * A_ROW_B + (lane >> 4) * 16);
    uint32_t b_lm_off = (uint32_t)(A_STAGE_BYTES + (lane & 15) * B_ROW_B
                                   + (wn + (lane >> 4) * 8) * 2);

    float acc[4][4][4];
    #pragma unroll
    for (int mi = 0; mi < 4; mi++)
        #pragma unroll
        for (int ni = 0; ni < 4; ni++)
            #pragma unroll
            for (int j = 0; j < 4; j++) acc[mi][ni][j] = 0.f;

    #define PF1(kt_, s_) do { \
        uint32_t ao = a_sm + (s_) * STAGE_BYTES; \
        uint32_t bo = b_sm + (s_) * STAGE_BYTES; \
        const __half* ag = agp + (kt_) * KT; \
        const __half* bg = bgp + (size_t)(kt_) * KT * Hq; \
        cp16(ao,      ag,     asz); cp16(ao + 16, ag + 8, asz); \
        cp16(bo,      bg,     16);  cp16(bo + 16, bg + 8, 16); \
    } while (0)

    PF1(0, 0); CP_COMMIT();
    PF1(1, 1); CP_COMMIT();

    const int NKT = Dq / KT;   // 32
    for (int kt = 0; kt < NKT; kt++) {
        int s = kt % NSTAGE;
        CP_WAIT1();
        __syncthreads();
        if (kt + 2 < NKT) PF1(kt + 2, (kt + 2) % NSTAGE);
        CP_COMMIT();
        uint32_t sbase = sm0 + s * STAGE_BYTES;
        uint32_t a_lm = sbase + a_lm_off;
        uint32_t b_lm = sbase + b_lm_off;
        #pragma unroll
        for (int ks8 = 0; ks8 < 2; ks8++) {   // two k16 steps per k-tile
            uint32_t af[4][4], bf[4][2];
            #pragma unroll
            for (int mi = 0; mi < 4; mi++)
                LDSM_X4(af[mi][0], af[mi][1], af[mi][2], af[mi][3],
                        a_lm + mi * (16 * A_ROW_B) + ks8 * 32);
            #pragma unroll
            for (int n2 = 0; n2 < 2; n2++)
                LDSM_X4_T(bf[2*n2][0], bf[2*n2][1], bf[2*n2+1][0], bf[2*n2+1][1],
                          b_lm + n2 * 32 + ks8 * (16 * B_ROW_B));
            #pragma unroll
            for (int mi = 0; mi < 4; mi++)
                #pragma unroll
                for (int ni = 0; ni < 4; ni++)
                    mma16(acc[mi][ni], af[mi][0], af[mi][1], af[mi][2], af[mi][3],
                          bf[ni][0], bf[ni][1]);
        }
    }

    // epilogue: bias + exact gelu -> g_h (fp16)
    #pragma unroll
    for (int mi = 0; mi < 4; mi++) {
        #pragma unroll
        for (int h = 0; h < 2; h++) {
            int r = wm + mi * 16 + qr + h * 8;
            if (m0 + r < rows) {
                size_t gr = (size_t)(base + m0 + r);
                __half* hrow = g_h + gr * Hq;
                #pragma unroll
                for (int ni = 0; ni < 4; ni++) {
                    int c = n0 + wn + ni * 8 + qc * 2;
                    float u = acc[mi][ni][h*2+0] + b1[e * Hq + c];
                    float v = acc[mi][ni][h*2+1] + b1[e * Hq + c + 1];
                    *reinterpret_cast<__half2*>(hrow + c) =
                        __floats2half2_rn(gelu_exact(u), gelu_exact(v));
                }
            }
        }
    }
}

// -------------------- GEMM2: z += gate * (H @ W2[e] + b2[e]) --------------
__global__ __launch_bounds__(256, 2) void gemm2_k(const float* __restrict__ b2) {
    int e  = blockIdx.x >> 6;
    int mt = blockIdx.x & 63;
    int rows = g_count[e];
    int m0 = mt * 128;
    if (m0 >= rows) return;
    int base = g_offset[e];
    int n0 = blockIdx.y * 128;

    extern __shared__ __align__(16) char smraw[];
    uint32_t sm0 = (uint32_t)__cvta_generic_to_shared(smraw);
    int tid = threadIdx.x;

    int arow = tid >> 1;
    bool av  = (m0 + arow) < rows;
    const __half* agp = g_h + (size_t)(base + m0 + (av ? arow : 0)) * Hq + (tid & 1) * 16;
    int asz = av ? 16 : 0;
    uint32_t a_sm = sm0 + arow * A_ROW_B + (tid & 1) * 32;

    int bkr = tid >> 3;
    int bnb = (tid & 7) * 16;
    const __half* bgp = g_w2h + (size_t)e * Hq * Dq + (size_t)bkr * Dq + n0 + bnb;
    uint32_t b_sm = sm0 + A_STAGE_BYTES + bkr * B_ROW_B + bnb * 2;

    int warp = tid >> 5, lane = tid & 31;
    int wm = (warp >> 2) * 64, wn = (warp & 3) * 32;
    int qr = lane >> 2, qc = lane & 3;
    uint32_t a_lm_off = (uint32_t)((wm + (lane & 15)) * A_ROW_B + (lane >> 4) * 16);
    uint32_t b_lm_off = (uint32_t)(A_STAGE_BYTES + (lane & 15) * B_ROW_B
                                   + (wn + (lane >> 4) * 8) * 2);

    float acc[4][4][4];
    #pragma unroll
    for (int mi = 0; mi < 4; mi++)
        #pragma unroll
        for (int ni = 0; ni < 4; ni++)
            #pragma unroll
            for (int j = 0; j < 4; j++) acc[mi][ni][j] = 0.f;

    #define PF2(kt_, s_) do { \
        uint32_t ao = a_sm + (s_) * STAGE_BYTES; \
        uint32_t bo = b_sm + (s_) * STAGE_BYTES; \
        const __half* ag = agp + (kt_) * KT; \
        const __half* bg = bgp + (size_t)(kt_) * KT * Dq; \
        cp16(ao,      ag,     asz); cp16(ao + 16, ag + 8, asz); \
        cp16(bo,      bg,     16);  cp16(bo + 16, bg + 8, 16); \
    } while (0)

    PF2(0, 0); CP_COMMIT();
    PF2(1, 1); CP_COMMIT();

    const int NKT = Hq / KT;   // 64
    for (int kt = 0; kt < NKT; kt++) {
        int s = kt % NSTAGE;
        CP_WAIT1();
        __syncthreads();
        if (kt + 2 < NKT) PF2(kt + 2, (kt + 2) % NSTAGE);
        CP_COMMIT();
        uint32_t sbase = sm0 + s * STAGE_BYTES;
        uint32_t a_lm = sbase + a_lm_off;
        uint32_t b_lm = sbase + b_lm_off;
        #pragma unroll
        for (int ks8 = 0; ks8 < 2; ks8++) {
            uint32_t af[4][4], bf[4][2];
            #pragma unroll
            for (int mi = 0; mi < 4; mi++)
                LDSM_X4(af[mi][0], af[mi][1], af[mi][2], af[mi][3],
                        a_lm + mi * (16 * A_ROW_B) + ks8 * 32);
            #pragma unroll
            for (int n2 = 0; n2 < 2; n2++)
                LDSM_X4_T(bf[2*n2][0], bf[2*n2][1], bf[2*n2+1][0], bf[2*n2+1][1],
                          b_lm + n2 * 32 + ks8 * (16 * B_ROW_B));
            #pragma unroll
            for (int mi = 0; mi < 4; mi++)
                #pragma unroll
                for (int ni = 0; ni < 4; ni++)
                    mma16(acc[mi][ni], af[mi][0], af[mi][1], af[mi][2], af[mi][3],
                          bf[ni][0], bf[ni][1]);
        }
    }

    // epilogue: gate * (acc + b2) scattered into residual accumulator
    #pragma unroll
    for (int mi = 0; mi < 4; mi++) {
        #pragma unroll
        for (int h = 0; h < 2; h++) {
            int r = wm + mi * 16 + qr + h * 8;
            if (m0 + r < rows) {
                int gr = base + m0 + r;
                int tok  = g_row_token[gr];
                float gt = g_row_gate[gr];
                float* zr = g_z + (size_t)tok * Dq;
                #pragma unroll
                for (int ni = 0; ni < 4; ni++) {
                    int c = n0 + wn + ni * 8 + qc * 2;
                    atomicAdd(&zr[c],     gt * (acc[mi][ni][h*2+0] + b2[e * Dq + c]));
                    atomicAdd(&zr[c + 1], gt * (acc[mi][ni][h*2+1] + b2[e * Dq + c + 1]));
                }
            }
        }
    }
}

// -------------------- layernorm: one block (256 thr) per token ------------
__global__ void ln_k(const float* __restrict__ gamma,
                     const float* __restrict__ beta,
                     float* __restrict__ out) {
    int t = blockIdx.x;
    int tid = threadIdx.x;
    const float4* zr = reinterpret_cast<const float4*>(g_z + (size_t)t * Dq);
    float4 v = zr[tid];
    float s  = v.x + v.y + v.z + v.w;
    float ss = v.x*v.x + v.y*v.y + v.z*v.z + v.w*v.w;

    #pragma unroll
    for (int o = 16; o > 0; o >>= 1) {
        s  += __shfl_down_sync(0xffffffffu, s, o);
        ss += __shfl_down_sync(0xffffffffu, ss, o);
    }
    __shared__ float rs[8], rss[8];
    int warp = tid >> 5, lane = tid & 31;
    if (lane == 0) { rs[warp] = s; rss[warp] = ss; }
    __syncthreads();
    if (warp == 0) {
        float a = (lane < 8) ? rs[lane] : 0.f;
        float b = (lane < 8) ? rss[lane] : 0.f;
        #pragma unroll
        for (int o = 4; o > 0; o >>= 1) {
            a += __shfl_down_sync(0xffffffffu, a, o);
            b += __shfl_down_sync(0xffffffffu, b, o);
        }
        if (lane == 0) { rs[0] = a; rss[0] = b; }
    }
    __syncthreads();
    float mu  = rs[0] * (1.f / Dq);
    float var = rss[0] * (1.f / Dq) - mu * mu;
    float rstd = rsqrtf(var + 1e-5f);

    float4 g = reinterpret_cast<const float4*>(gamma)[tid];
    float4 bta = reinterpret_cast<const float4*>(beta)[tid];
    float4 o4;
    o4.x = (v.x - mu) * rstd * g.x + bta.x;
    o4.y = (v.y - mu) * rstd * g.y + bta.y;
    o4.z = (v.z - mu) * rstd * g.z + bta.z;
    o4.w = (v.w - mu) * rstd * g.w + bta.w;
    reinterpret_cast<float4*>(out + (size_t)t * Dq)[tid] = o4;
}

// -------------------- launch ----------------------------------------------
extern "C" void kernel_launch(void* const* d_in, const int* in_sizes, int n_in,
                              void* d_out, int out_size) {
    const float* x     = (const float*)d_in[0];
    const float* gw    = (const float*)d_in[1];
    const float* gb    = (const float*)d_in[2];
    const float* W1    = (const float*)d_in[3];
    const float* b1    = (const float*)d_in[4];
    const float* W2    = (const float*)d_in[5];
    const float* b2    = (const float*)d_in[6];
    const float* gamma = (const float*)d_in[7];
    const float* beta  = (const float*)d_in[8];
    float* out = (float*)d_out;

    static bool attr_set = false;
    if (!attr_set) {
        cudaFuncSetAttribute(gemm1_k, cudaFuncAttributeMaxDynamicSharedMemorySize, SMEM_BYTES);
        cudaFuncSetAttribute(gemm2_k, cudaFuncAttributeMaxDynamicSharedMemorySize, SMEM_BYTES);
        attr_set = true;
    }

    __half* xh;  cudaGetSymbolAddress((void**)&xh,  g_xh);
    __half* w1h; cudaGetSymbolAddress((void**)&w1h, g_w1h);
    __half* w2h; cudaGetSymbolAddress((void**)&w2h, g_w2h);

    // fp32 -> fp16 conversions (8 elems per thread)
    cvt_k<<<(Nq*Dq/8)/256, 256>>>((const float4*)x,  (uint4*)xh);
    cvt_k<<<((size_t)Eq*Dq*Hq/8)/256, 256>>>((const float4*)W1, (uint4*)w1h);
    cvt_k<<<((size_t)Eq*Hq*Dq/8)/256, 256>>>((const float4*)W2, (uint4*)w2h);

    init_k<<<1, 32>>>();
    router_k<<<Nq / 8, 256>>>(x, gw, gb);
    finalize_k<<<1, 32>>>(out + (size_t)Nq * Dq);
    scatter_k<<<Nq / 256, 256>>>();
    zinit_k<<<(Nq * Dq / 4) / 256, 256>>>(x);
    gemm1_k<<<dim3(Eq * MTILES, Hq / 128), 256, SMEM_BYTES>>>(b1);
    gemm2_k<<<dim3(Eq * MTILES, Dq / 128), 256, SMEM_BYTES>>>(b2);
    ln_k<<<Nq, 256>>>(gamma, beta, out);
    (void)in_sizes; (void)n_in; (void)out_size;
}